// round 1
// baseline (speedup 1.0000x reference)
#include <cuda_runtime.h>
#include <math.h>

#define CCH 62
#define TT  2000
#define NB  256
#define TIL 128
#define NTILE ((TT + TIL - 1) / TIL)   // 16

// scratch: per-batch padded 64x64 raw covariance of x
__device__ float g_cx[NB * 64 * 64];

// ---------------------------------------------------------------------------
// Kernel 1: per-batch covariance of raw x (centered), padded to 64x64.
// Cx = (sum_t x x^T - (sum x)(sum x)^T / T) / (T-1)
// ---------------------------------------------------------------------------
__global__ __launch_bounds__(256) void cov_kernel(const float* __restrict__ x)
{
    __shared__ float xs[64 * 129];
    __shared__ float ssum[64];

    const int b   = blockIdx.x;
    const int tid = threadIdx.x;
    const int ti  = tid >> 4;
    const int tj  = tid & 15;

    float acc[16];
#pragma unroll
    for (int r = 0; r < 16; r++) acc[r] = 0.f;
    float mysum0 = 0.f, mysum1 = 0.f;

    const float* xb = x + (size_t)b * CCH * TT;

    for (int tile = 0; tile < NTILE; tile++) {
        const int t0 = tile * TIL;
        // load tile [64 x 128] (rows >= 62 and t >= TT zero-filled)
        for (int idx = tid; idx < 64 * TIL; idx += 256) {
            const int c  = idx >> 7;
            const int tl = idx & 127;
            const int t  = t0 + tl;
            float v = 0.f;
            if (c < CCH && t < TT) v = xb[c * TT + t];
            xs[c * 129 + tl] = v;
        }
        __syncthreads();

        // channel sums (for the mean correction)
        if (tid < CCH) {
            const float* rp = xs + tid * 129;
#pragma unroll 4
            for (int tl = 0; tl < TIL; tl += 2) {
                mysum0 += rp[tl];
                mysum1 += rp[tl + 1];
            }
        }

        const float* r0 = xs + (4 * ti + 0) * 129;
        const float* r1 = xs + (4 * ti + 1) * 129;
        const float* r2 = xs + (4 * ti + 2) * 129;
        const float* r3 = xs + (4 * ti + 3) * 129;
        const float* c0 = xs + (4 * tj + 0) * 129;
        const float* c1 = xs + (4 * tj + 1) * 129;
        const float* c2 = xs + (4 * tj + 2) * 129;
        const float* c3 = xs + (4 * tj + 3) * 129;

#pragma unroll 2
        for (int tl = 0; tl < TIL; tl++) {
            const float a0 = r0[tl], a1 = r1[tl], a2 = r2[tl], a3 = r3[tl];
            const float b0 = c0[tl], b1 = c1[tl], b2 = c2[tl], b3 = c3[tl];
            acc[0]  += a0 * b0; acc[1]  += a0 * b1; acc[2]  += a0 * b2; acc[3]  += a0 * b3;
            acc[4]  += a1 * b0; acc[5]  += a1 * b1; acc[6]  += a1 * b2; acc[7]  += a1 * b3;
            acc[8]  += a2 * b0; acc[9]  += a2 * b1; acc[10] += a2 * b2; acc[11] += a2 * b3;
            acc[12] += a3 * b0; acc[13] += a3 * b1; acc[14] += a3 * b2; acc[15] += a3 * b3;
        }
        __syncthreads();
    }

    if (tid < 64) ssum[tid] = mysum0 + mysum1;   // rows >= 62 accumulated zeros
    __syncthreads();

    float* outp = g_cx + b * 4096;
#pragma unroll
    for (int r = 0; r < 4; r++) {
#pragma unroll
        for (int u = 0; u < 4; u++) {
            const int i = 4 * ti + r;
            const int j = 4 * tj + u;
            const float v = (acc[r * 4 + u] - ssum[i] * ssum[j] * (1.f / 2000.f)) * (1.f / 1999.f);
            outp[i * 64 + j] = v;
        }
    }
}

// ---------------------------------------------------------------------------
// Kernel 2: per-batch  A = W Cx W^T + eps I  ->  Jacobi eigh  ->  log-map ->
//           triu vectorize -> proj+relu -> head.  One CTA (256 thr) per batch.
// ---------------------------------------------------------------------------
__device__ __forceinline__ void pair_pq(int r, int k, int& p, int& q)
{
    if (k == 0) { p = 63; q = r; }
    else { p = (r + k) % 63; q = (r + 63 - k) % 63; }
}

__global__ __launch_bounds__(256) void eig_kernel(
    const float* __restrict__ conv_w,
    const float* __restrict__ proj_w, const float* __restrict__ proj_b,
    const float* __restrict__ head_w, const float* __restrict__ head_b,
    float* __restrict__ out)
{
    __shared__ float Asm[64 * 65];   // stride 65 -> conflict-free column updates
    __shared__ float Vsm[64 * 64];   // rows = rows of accumulated rotation Q
    __shared__ float Wbuf[62 * 62];  // W in prologue; reused as scratch after

    float* vec  = Wbuf;              // [1953]
    float* csC  = Wbuf + 2048;       // [32]
    float* csS  = Wbuf + 2080;       // [32]
    float* logl = Wbuf + 2112;       // [64]
    float* feat = Wbuf + 2176;       // [64]
    float* red  = Wbuf + 2240;       // [9]

    const int b   = blockIdx.x;
    const int tid = threadIdx.x;
    const int ti  = tid >> 4;
    const int tj  = tid & 15;

    // ---- load Cx (into Asm) and W ----
    for (int idx = tid; idx < 4096; idx += 256)
        Asm[(idx >> 6) * 65 + (idx & 63)] = g_cx[b * 4096 + idx];
    for (int idx = tid; idx < 62 * 62; idx += 256) Wbuf[idx] = conv_w[idx];
    __syncthreads();

    // ---- M = W * Cx  -> Vsm ----
    {
        float acc[16];
#pragma unroll
        for (int r = 0; r < 16; r++) acc[r] = 0.f;
        for (int k = 0; k < 62; k++) {
            float wv[4], cv[4];
#pragma unroll
            for (int r = 0; r < 4; r++) {
                const int i = 4 * ti + r;
                wv[r] = (i < 62) ? Wbuf[i * 62 + k] : 0.f;
            }
#pragma unroll
            for (int u = 0; u < 4; u++) cv[u] = Asm[k * 65 + 4 * tj + u];
#pragma unroll
            for (int r = 0; r < 4; r++)
#pragma unroll
                for (int u = 0; u < 4; u++) acc[r * 4 + u] += wv[r] * cv[u];
        }
#pragma unroll
        for (int r = 0; r < 4; r++)
#pragma unroll
            for (int u = 0; u < 4; u++)
                Vsm[(4 * ti + r) * 64 + 4 * tj + u] = acc[r * 4 + u];
    }
    __syncthreads();

    // ---- A = M * W^T  -> Asm (overwrites Cx; Vsm/Wbuf are the only reads) ----
    {
        float acc[16];
#pragma unroll
        for (int r = 0; r < 16; r++) acc[r] = 0.f;
        for (int k = 0; k < 62; k++) {
            float mv[4], wv[4];
#pragma unroll
            for (int r = 0; r < 4; r++) mv[r] = Vsm[(4 * ti + r) * 64 + k];
#pragma unroll
            for (int u = 0; u < 4; u++) {
                const int j = 4 * tj + u;
                wv[u] = (j < 62) ? Wbuf[j * 62 + k] : 0.f;
            }
#pragma unroll
            for (int r = 0; r < 4; r++)
#pragma unroll
                for (int u = 0; u < 4; u++) acc[r * 4 + u] += mv[r] * wv[u];
        }
#pragma unroll
        for (int r = 0; r < 4; r++)
#pragma unroll
            for (int u = 0; u < 4; u++)
                Asm[(4 * ti + r) * 65 + 4 * tj + u] = acc[r * 4 + u];
    }
    __syncthreads();

    // ---- symmetrize + SPD eps + pad diag ----
    {
        float v[16];
#pragma unroll
        for (int r = 0; r < 4; r++)
#pragma unroll
            for (int u = 0; u < 4; u++) {
                const int i = 4 * ti + r, j = 4 * tj + u;
                v[r * 4 + u] = 0.5f * (Asm[i * 65 + j] + Asm[j * 65 + i]);
            }
        __syncthreads();
#pragma unroll
        for (int r = 0; r < 4; r++)
#pragma unroll
            for (int u = 0; u < 4; u++) {
                const int i = 4 * ti + r, j = 4 * tj + u;
                float val = v[r * 4 + u];
                if (i == j) val = (i < 62) ? val + 1e-3f : 1.0f;
                Asm[i * 65 + j] = val;
            }
    }
    // ---- V = I ----
    for (int idx = tid; idx < 4096; idx += 256)
        Vsm[idx] = ((idx >> 6) == (idx & 63)) ? 1.f : 0.f;
    __syncthreads();

    // ---- parallel cyclic Jacobi, tournament schedule ----
    const float tol = 1e-6f;
    for (int sweep = 0; sweep < 12; sweep++) {
        for (int r = 0; r < 63; r++) {
            if (tid < 32) {
                int p, q; pair_pq(r, tid, p, q);
                const float app = Asm[p * 65 + p];
                const float aqq = Asm[q * 65 + q];
                const float apq = Asm[p * 65 + q];
                float c = 1.f, s = 0.f;
                if (fabsf(apq) > 1e-12f) {
                    const float tau = (aqq - app) / (2.f * apq);
                    const float tt  = ((tau >= 0.f) ? 1.f : -1.f) /
                                      (fabsf(tau) + sqrtf(1.f + tau * tau));
                    c = 1.f / sqrtf(1.f + tt * tt);
                    s = tt * c;
                }
                csC[tid] = c; csS[tid] = s;
            }
            __syncthreads();

            // phase 1: rotate rows of A and rows of V (disjoint rows per pair)
#pragma unroll
            for (int it = 0; it < 16; it++) {
                const int item = tid + (it << 8);
                const int kk   = item >> 7;          // pair index, warp-uniform
                const int rem  = item & 127;
                const int j    = rem & 63;
                const float c = csC[kk], s = csS[kk];
                if (s != 0.f) {
                    int p, q; pair_pq(r, kk, p, q);
                    if (rem < 64) {
                        const float xp = Asm[p * 65 + j], xq = Asm[q * 65 + j];
                        Asm[p * 65 + j] = c * xp - s * xq;
                        Asm[q * 65 + j] = s * xp + c * xq;
                    } else {
                        const float xp = Vsm[p * 64 + j], xq = Vsm[q * 64 + j];
                        Vsm[p * 64 + j] = c * xp - s * xq;
                        Vsm[q * 64 + j] = s * xp + c * xq;
                    }
                }
            }
            __syncthreads();

            // phase 2: rotate columns of A (disjoint columns per pair)
#pragma unroll
            for (int it = 0; it < 8; it++) {
                const int item = tid + (it << 8);
                const int kk   = item >> 6;
                const int i    = item & 63;
                const float c = csC[kk], s = csS[kk];
                if (s != 0.f) {
                    int p, q; pair_pq(r, kk, p, q);
                    const float xp = Asm[i * 65 + p], xq = Asm[i * 65 + q];
                    Asm[i * 65 + p] = c * xp - s * xq;
                    Asm[i * 65 + q] = s * xp + c * xq;
                }
            }
            __syncthreads();
        }

        // convergence: max |offdiag|
        float m = 0.f;
        for (int idx = tid; idx < 4096; idx += 256) {
            const int i = idx >> 6, j = idx & 63;
            if (i != j) m = fmaxf(m, fabsf(Asm[i * 65 + j]));
        }
#pragma unroll
        for (int off = 16; off; off >>= 1)
            m = fmaxf(m, __shfl_down_sync(0xffffffffu, m, off));
        if ((tid & 31) == 0) red[tid >> 5] = m;
        __syncthreads();
        if (tid == 0) {
            float mm = red[0];
#pragma unroll
            for (int w = 1; w < 8; w++) mm = fmaxf(mm, red[w]);
            red[8] = mm;
        }
        __syncthreads();
        if (red[8] < tol) break;
    }

    // ---- log eigenvalues ----
    if (tid < 64) {
        const float d = Asm[tid * 65 + tid];
        logl[tid] = logf(fmaxf(d, 1e-6f));
    }
    __syncthreads();
    // scale: Asm[k][i] = logl[k] * Q[k][i]
    for (int idx = tid; idx < 4096; idx += 256) {
        const int k = idx >> 6, i = idx & 63;
        Asm[k * 65 + i] = logl[k] * Vsm[idx];
    }
    __syncthreads();

    // ---- triu vectorize: vec(i,j) = sum_k logl[k] Q[k][i] Q[k][j] ----
    for (int idx = tid; idx < 1953; idx += 256) {
        int i = (int)((125.0f - sqrtf(15625.0f - 8.0f * (float)idx)) * 0.5f);
        if (i < 0) i = 0;
        if (i > 61) i = 61;
        while (i < 61 && (i + 1) * (125 - (i + 1)) / 2 <= idx) i++;
        while (i > 0 && i * (125 - i) / 2 > idx) i--;
        const int j = i + (idx - i * (125 - i) / 2);
        float acc = 0.f;
#pragma unroll 8
        for (int k = 0; k < 64; k++) acc += Asm[k * 65 + i] * Vsm[k * 64 + j];
        vec[idx] = acc;
    }
    __syncthreads();

    // ---- MLP: feat = relu(vec @ proj^T + b), 8 outputs per warp ----
    {
        const int w = tid >> 5, lane = tid & 31;
#pragma unroll
        for (int hh = 0; hh < 8; hh++) {
            const int h = (w << 3) + hh;
            const float* pw = proj_w + h * 1953;
            float acc = 0.f;
            for (int i = lane; i < 1953; i += 32) acc += vec[i] * pw[i];
#pragma unroll
            for (int off = 16; off; off >>= 1)
                acc += __shfl_down_sync(0xffffffffu, acc, off);
            if (lane == 0) feat[h] = fmaxf(acc + proj_b[h], 0.f);
        }
    }
    __syncthreads();

    // ---- head: 3 logits ----
    if (tid < 3) {
        float acc = head_b[tid];
        const float* hw = head_w + tid * 64;
#pragma unroll
        for (int h = 0; h < 64; h++) acc += feat[h] * hw[h];
        out[b * 3 + tid] = acc;
    }
}

// ---------------------------------------------------------------------------
extern "C" void kernel_launch(void* const* d_in, const int* in_sizes, int n_in,
                              void* d_out, int out_size)
{
    const float* x      = (const float*)d_in[0];
    const float* conv_w = (const float*)d_in[1];
    // d_in[2] = conv_b: cancels exactly under mean-centering; unused.
    const float* proj_w = (const float*)d_in[3];
    const float* proj_b = (const float*)d_in[4];
    const float* head_w = (const float*)d_in[5];
    const float* head_b = (const float*)d_in[6];

    int B = in_sizes[0] / (CCH * TT);
    if (B > NB) B = NB;

    cov_kernel<<<B, 256>>>(x);
    eig_kernel<<<B, 256>>>(conv_w, proj_w, proj_b, head_w, head_b, (float*)d_out);
}

// round 2
// speedup vs baseline: 1.5867x; 1.5867x over previous
#include <cuda_runtime.h>
#include <math.h>

#define CCH 62
#define TT  2000
#define NB  256
#define TIL 128
#define NTILE ((TT + TIL - 1) / TIL)   // 16

// scratch: per-batch padded 64x64 raw covariance of x
__device__ float g_cx[NB * 64 * 64];

// ---------------------------------------------------------------------------
// Kernel 1: per-batch covariance of raw x (centered), padded to 64x64.
// Triangular block mapping: only 136 of 256 threads compute 4x4 blocks
// (upper block-triangle), results mirrored on store. float2 smem loads.
// ---------------------------------------------------------------------------
__global__ __launch_bounds__(256, 2) void cov_kernel(const float* __restrict__ x)
{
    __shared__ float xs[64 * 130];
    __shared__ float ssum[64];

    const int b   = blockIdx.x;
    const int tid = threadIdx.x;

    // triangular 4x4-block decode: tid < 136 -> (bi, bj), bi <= bj
    int bi = 0, bj = 0;
    const bool act = (tid < 136);
    if (act) {
        int z = tid;
        while (z >= 16 - bi) { z -= 16 - bi; bi++; }
        bj = bi + z;
    }

    float acc[16];
#pragma unroll
    for (int r = 0; r < 16; r++) acc[r] = 0.f;
    float mysum = 0.f;

    const float* xb = x + (size_t)b * CCH * TT;

    for (int tile = 0; tile < NTILE; tile++) {
        const int t0 = tile * TIL;
        // load tile [64 x 128] (rows >= 62 and t >= TT zero-filled), stride 130
        for (int idx = tid; idx < 64 * TIL; idx += 256) {
            const int c  = idx >> 7;
            const int tl = idx & 127;
            const int t  = t0 + tl;
            float v = 0.f;
            if (c < CCH && t < TT) v = xb[c * TT + t];
            xs[c * 130 + tl] = v;
        }
        __syncthreads();

        // channel sums (for the mean correction)
        if (tid < CCH) {
            const float2* rp = (const float2*)(xs + tid * 130);
#pragma unroll 8
            for (int tl = 0; tl < 64; tl++) {
                const float2 v = rp[tl];
                mysum += v.x + v.y;
            }
        }

        if (act) {
            const float2* r0 = (const float2*)(xs + (4 * bi + 0) * 130);
            const float2* r1 = (const float2*)(xs + (4 * bi + 1) * 130);
            const float2* r2 = (const float2*)(xs + (4 * bi + 2) * 130);
            const float2* r3 = (const float2*)(xs + (4 * bi + 3) * 130);
            const float2* c0 = (const float2*)(xs + (4 * bj + 0) * 130);
            const float2* c1 = (const float2*)(xs + (4 * bj + 1) * 130);
            const float2* c2 = (const float2*)(xs + (4 * bj + 2) * 130);
            const float2* c3 = (const float2*)(xs + (4 * bj + 3) * 130);

#pragma unroll 4
            for (int tl = 0; tl < 64; tl++) {
                const float2 a0 = r0[tl], a1 = r1[tl], a2 = r2[tl], a3 = r3[tl];
                const float2 b0 = c0[tl], b1 = c1[tl], b2 = c2[tl], b3 = c3[tl];
                acc[0]  += a0.x * b0.x + a0.y * b0.y;
                acc[1]  += a0.x * b1.x + a0.y * b1.y;
                acc[2]  += a0.x * b2.x + a0.y * b2.y;
                acc[3]  += a0.x * b3.x + a0.y * b3.y;
                acc[4]  += a1.x * b0.x + a1.y * b0.y;
                acc[5]  += a1.x * b1.x + a1.y * b1.y;
                acc[6]  += a1.x * b2.x + a1.y * b2.y;
                acc[7]  += a1.x * b3.x + a1.y * b3.y;
                acc[8]  += a2.x * b0.x + a2.y * b0.y;
                acc[9]  += a2.x * b1.x + a2.y * b1.y;
                acc[10] += a2.x * b2.x + a2.y * b2.y;
                acc[11] += a2.x * b3.x + a2.y * b3.y;
                acc[12] += a3.x * b0.x + a3.y * b0.y;
                acc[13] += a3.x * b1.x + a3.y * b1.y;
                acc[14] += a3.x * b2.x + a3.y * b2.y;
                acc[15] += a3.x * b3.x + a3.y * b3.y;
            }
        }
        __syncthreads();
    }

    if (tid < 64) ssum[tid] = (tid < CCH) ? mysum : 0.f;
    __syncthreads();

    if (act) {
        float* outp = g_cx + b * 4096;
#pragma unroll
        for (int r = 0; r < 4; r++) {
#pragma unroll
            for (int u = 0; u < 4; u++) {
                const int i = 4 * bi + r;
                const int j = 4 * bj + u;
                const float v =
                    (acc[r * 4 + u] - ssum[i] * ssum[j] * (1.f / 2000.f)) * (1.f / 1999.f);
                outp[i * 64 + j] = v;
                outp[j * 64 + i] = v;
            }
        }
    }
}

// ---------------------------------------------------------------------------
// Kernel 2: A = W Cx W^T + eps I  ->  Jacobi eigh  ->  log-map -> triu ->
//           proj+relu -> head.  One CTA (256 thr) per batch, 2 CTAs/SM.
// ---------------------------------------------------------------------------
__device__ __forceinline__ void pair_pq(int r, int k, int& p, int& q)
{
    if (k == 0) { p = 63; q = r; }
    else { p = (r + k) % 63; q = (r + 63 - k) % 63; }
}

#define TBL_OFF 2186   // float offset of pair table inside Wbuf scratch

__global__ __launch_bounds__(256, 2) void eig_kernel(
    const float* __restrict__ conv_w,
    const float* __restrict__ proj_w, const float* __restrict__ proj_b,
    const float* __restrict__ head_w, const float* __restrict__ head_b,
    float* __restrict__ out)
{
    __shared__ float Asm[64 * 65];   // stride 65 -> conflict-free column updates
    __shared__ float Vsm[64 * 64];   // rows = rows of accumulated rotation Q
    __shared__ float Wbuf[62 * 62];  // W in prologue; scratch after

    float* vec  = Wbuf;              // [1953]
    float* logl = Wbuf + 2048;       // [64]
    float* feat = Wbuf + 2112;       // [64]
    float* red  = Wbuf + 2176;       // [9]
    unsigned short* tbl = (unsigned short*)(Wbuf + TBL_OFF);  // [63*32]

    const int b   = blockIdx.x;
    const int tid = threadIdx.x;
    const int ti  = tid >> 4;
    const int tj  = tid & 15;
    const int lane = tid & 31;

    // ---- load Cx (into Asm) and W ----
    for (int idx = tid; idx < 4096; idx += 256)
        Asm[(idx >> 6) * 65 + (idx & 63)] = g_cx[b * 4096 + idx];
    for (int idx = tid; idx < 62 * 62; idx += 256) Wbuf[idx] = conv_w[idx];
    __syncthreads();

    // ---- M = W * Cx  -> Vsm ----
    {
        float acc[16];
#pragma unroll
        for (int r = 0; r < 16; r++) acc[r] = 0.f;
        for (int k = 0; k < 62; k++) {
            float wv[4], cv[4];
#pragma unroll
            for (int r = 0; r < 4; r++) {
                const int i = 4 * ti + r;
                wv[r] = (i < 62) ? Wbuf[i * 62 + k] : 0.f;
            }
#pragma unroll
            for (int u = 0; u < 4; u++) cv[u] = Asm[k * 65 + 4 * tj + u];
#pragma unroll
            for (int r = 0; r < 4; r++)
#pragma unroll
                for (int u = 0; u < 4; u++) acc[r * 4 + u] += wv[r] * cv[u];
        }
#pragma unroll
        for (int r = 0; r < 4; r++)
#pragma unroll
            for (int u = 0; u < 4; u++)
                Vsm[(4 * ti + r) * 64 + 4 * tj + u] = acc[r * 4 + u];
    }
    __syncthreads();

    // ---- A = M * W^T  -> Asm ----
    {
        float acc[16];
#pragma unroll
        for (int r = 0; r < 16; r++) acc[r] = 0.f;
        for (int k = 0; k < 62; k++) {
            float mv[4], wv[4];
#pragma unroll
            for (int r = 0; r < 4; r++) mv[r] = Vsm[(4 * ti + r) * 64 + k];
#pragma unroll
            for (int u = 0; u < 4; u++) {
                const int j = 4 * tj + u;
                wv[u] = (j < 62) ? Wbuf[j * 62 + k] : 0.f;
            }
#pragma unroll
            for (int r = 0; r < 4; r++)
#pragma unroll
                for (int u = 0; u < 4; u++) acc[r * 4 + u] += mv[r] * wv[u];
        }
#pragma unroll
        for (int r = 0; r < 4; r++)
#pragma unroll
            for (int u = 0; u < 4; u++)
                Asm[(4 * ti + r) * 65 + 4 * tj + u] = acc[r * 4 + u];
    }
    __syncthreads();

    // ---- symmetrize + SPD eps + pad diag; also build pair table ----
    {
        float v[16];
#pragma unroll
        for (int r = 0; r < 4; r++)
#pragma unroll
            for (int u = 0; u < 4; u++) {
                const int i = 4 * ti + r, j = 4 * tj + u;
                v[r * 4 + u] = 0.5f * (Asm[i * 65 + j] + Asm[j * 65 + i]);
            }
        __syncthreads();
#pragma unroll
        for (int r = 0; r < 4; r++)
#pragma unroll
            for (int u = 0; u < 4; u++) {
                const int i = 4 * ti + r, j = 4 * tj + u;
                float val = v[r * 4 + u];
                if (i == j) val = (i < 62) ? val + 1e-3f : 1.0f;
                Asm[i * 65 + j] = val;
            }
    }
    // V = I
    for (int idx = tid; idx < 4096; idx += 256)
        Vsm[idx] = ((idx >> 6) == (idx & 63)) ? 1.f : 0.f;
    // pair schedule table (tournament)
    for (int idx = tid; idx < 63 * 32; idx += 256) {
        int p, q;
        pair_pq(idx >> 5, idx & 31, p, q);
        tbl[idx] = (unsigned short)(p | (q << 8));
    }
    __syncthreads();

    // ---- parallel cyclic Jacobi ----
    // phase1 geometry (constant per thread): rows of A for (tid&127)<64, rows of V otherwise
    const int  jcol = tid & 63;
    const bool doA  = ((tid >> 6) & 1) == 0;
    float* P        = doA ? Asm : Vsm;
    const int pstr  = doA ? 65 : 64;
    const int khi1  = tid >> 7;          // phase1: kk = 2*it + khi1
    const int khi2  = (tid >> 6) & 3;    // phase2: kk = 4*it + khi2

    const float tol = 1e-5f;
    for (int sweep = 0; sweep < 9; sweep++) {
        for (int r = 0; r < 63; r++) {
            const unsigned short* trow = tbl + r * 32;
            // rotation compute: every warp redundantly, lane k -> pair k
            float cReg = 1.f, sReg = 0.f;
            {
                const int pq = trow[lane];
                const int p = pq & 255, q = pq >> 8;
                const float app = Asm[p * 65 + p];
                const float aqq = Asm[q * 65 + q];
                const float apq = Asm[p * 65 + q];
                if (fabsf(apq) > 1e-12f) {
                    const float tau = (aqq - app) / (2.f * apq);
                    const float t2  = ((tau >= 0.f) ? 1.f : -1.f) /
                                      (fabsf(tau) + sqrtf(1.f + tau * tau));
                    cReg = rsqrtf(1.f + t2 * t2);
                    sReg = t2 * cReg;
                }
            }
            const bool anyrot = __ballot_sync(0xffffffffu, sReg != 0.f) != 0u;
            __syncthreads();

            if (anyrot) {
                // phase 1: rotate rows (A rows or V rows), 16 items, 2 half-batches
#pragma unroll
                for (int hb = 0; hb < 2; hb++) {
                    float vp[8], vq[8], cc[8], ss[8];
#pragma unroll
                    for (int it = 0; it < 8; it++) {
                        const int kk = 2 * (hb * 8 + it) + khi1;
                        cc[it] = __shfl_sync(0xffffffffu, cReg, kk);
                        ss[it] = __shfl_sync(0xffffffffu, sReg, kk);
                        if (ss[it] != 0.f) {
                            const int pq = trow[kk];
                            vp[it] = P[(pq & 255) * pstr + jcol];
                            vq[it] = P[(pq >> 8) * pstr + jcol];
                        }
                    }
#pragma unroll
                    for (int it = 0; it < 8; it++) {
                        if (ss[it] != 0.f) {
                            const int kk = 2 * (hb * 8 + it) + khi1;
                            const int pq = trow[kk];
                            P[(pq & 255) * pstr + jcol] = cc[it] * vp[it] - ss[it] * vq[it];
                            P[(pq >> 8) * pstr + jcol]  = ss[it] * vp[it] + cc[it] * vq[it];
                        }
                    }
                }
            }
            __syncthreads();

            if (anyrot) {
                // phase 2: rotate columns of A, 8 items
                float vp[8], vq[8], cc[8], ss[8];
#pragma unroll
                for (int it = 0; it < 8; it++) {
                    const int kk = 4 * it + khi2;
                    cc[it] = __shfl_sync(0xffffffffu, cReg, kk);
                    ss[it] = __shfl_sync(0xffffffffu, sReg, kk);
                    if (ss[it] != 0.f) {
                        const int pq = trow[kk];
                        vp[it] = Asm[jcol * 65 + (pq & 255)];
                        vq[it] = Asm[jcol * 65 + (pq >> 8)];
                    }
                }
#pragma unroll
                for (int it = 0; it < 8; it++) {
                    if (ss[it] != 0.f) {
                        const int kk = 4 * it + khi2;
                        const int pq = trow[kk];
                        Asm[jcol * 65 + (pq & 255)] = cc[it] * vp[it] - ss[it] * vq[it];
                        Asm[jcol * 65 + (pq >> 8)]  = ss[it] * vp[it] + cc[it] * vq[it];
                    }
                }
            }
            __syncthreads();
        }

        // convergence: max |offdiag|
        float m = 0.f;
        for (int idx = tid; idx < 4096; idx += 256) {
            const int i = idx >> 6, j = idx & 63;
            if (i != j) m = fmaxf(m, fabsf(Asm[i * 65 + j]));
        }
#pragma unroll
        for (int off = 16; off; off >>= 1)
            m = fmaxf(m, __shfl_down_sync(0xffffffffu, m, off));
        if (lane == 0) red[tid >> 5] = m;
        __syncthreads();
        if (tid == 0) {
            float mm = red[0];
#pragma unroll
            for (int w = 1; w < 8; w++) mm = fmaxf(mm, red[w]);
            red[8] = mm;
        }
        __syncthreads();
        if (red[8] < tol) break;
    }

    // ---- log eigenvalues ----
    if (tid < 64) {
        const float d = Asm[tid * 65 + tid];
        logl[tid] = logf(fmaxf(d, 1e-6f));
    }
    __syncthreads();
    // scale rows: Asm[k][i] = logl[k] * Q[k][i]
    for (int idx = tid; idx < 4096; idx += 256) {
        const int k = idx >> 6, i = idx & 63;
        Asm[k * 65 + i] = logl[k] * Vsm[idx];
    }
    __syncthreads();

    // ---- triu vectorize: vec(i,j) = sum_k logl[k] Q[k][i] Q[k][j] ----
    for (int idx = tid; idx < 1953; idx += 256) {
        int i = (int)((125.0f - sqrtf(15625.0f - 8.0f * (float)idx)) * 0.5f);
        if (i < 0) i = 0;
        if (i > 61) i = 61;
        while (i < 61 && (i + 1) * (125 - (i + 1)) / 2 <= idx) i++;
        while (i > 0 && i * (125 - i) / 2 > idx) i--;
        const int j = i + (idx - i * (125 - i) / 2);
        float acc = 0.f;
#pragma unroll 8
        for (int k = 0; k < 64; k++) acc += Asm[k * 65 + i] * Vsm[k * 64 + j];
        vec[idx] = acc;
    }
    __syncthreads();

    // ---- MLP: feat = relu(vec @ proj^T + b), 8 outputs per warp ----
    {
        const int w = tid >> 5;
#pragma unroll
        for (int hh = 0; hh < 8; hh++) {
            const int h = (w << 3) + hh;
            const float* pw = proj_w + h * 1953;
            float acc = 0.f;
            for (int i = lane; i < 1953; i += 32) acc += vec[i] * pw[i];
#pragma unroll
            for (int off = 16; off; off >>= 1)
                acc += __shfl_down_sync(0xffffffffu, acc, off);
            if (lane == 0) feat[h] = fmaxf(acc + proj_b[h], 0.f);
        }
    }
    __syncthreads();

    // ---- head: 3 logits ----
    if (tid < 3) {
        float acc = head_b[tid];
        const float* hw = head_w + tid * 64;
#pragma unroll
        for (int h = 0; h < 64; h++) acc += feat[h] * hw[h];
        out[b * 3 + tid] = acc;
    }
}

// ---------------------------------------------------------------------------
extern "C" void kernel_launch(void* const* d_in, const int* in_sizes, int n_in,
                              void* d_out, int out_size)
{
    const float* x      = (const float*)d_in[0];
    const float* conv_w = (const float*)d_in[1];
    // d_in[2] = conv_b: cancels exactly under mean-centering; unused.
    const float* proj_w = (const float*)d_in[3];
    const float* proj_b = (const float*)d_in[4];
    const float* head_w = (const float*)d_in[5];
    const float* head_b = (const float*)d_in[6];

    int B = in_sizes[0] / (CCH * TT);
    if (B > NB) B = NB;

    cov_kernel<<<B, 256>>>(x);
    eig_kernel<<<B, 256>>>(conv_w, proj_w, proj_b, head_w, head_b, (float*)d_out);
}

// round 3
// speedup vs baseline: 2.8453x; 1.7932x over previous
#include <cuda_runtime.h>
#include <math.h>

#define CCH 62
#define TT  2000
#define NB  256
#define TIL 128
#define NTILE ((TT + TIL - 1) / TIL)   // 16

// scratch: per-batch padded 64x64 raw covariance of x
__device__ float g_cx[NB * 64 * 64];

// ---------------------------------------------------------------------------
// Kernel 1: per-batch covariance of raw x (centered), padded to 64x64.
// Triangular 4x4-block mapping (136 active threads), float4 smem loads.
// ---------------------------------------------------------------------------
__global__ __launch_bounds__(256, 2) void cov_kernel(const float* __restrict__ x)
{
    __shared__ __align__(16) float xs[64 * 132];   // stride 132 floats = 528B (16B aligned)
    __shared__ float ssum[64];

    const int b   = blockIdx.x;
    const int tid = threadIdx.x;

    int bi = 0, bj = 0;
    const bool act = (tid < 136);
    if (act) {
        int z = tid;
        while (z >= 16 - bi) { z -= 16 - bi; bi++; }
        bj = bi + z;
    }

    float acc[16];
#pragma unroll
    for (int r = 0; r < 16; r++) acc[r] = 0.f;
    float mysum = 0.f;

    const float* xb = x + (size_t)b * CCH * TT;

    for (int tile = 0; tile < NTILE; tile++) {
        const int t0 = tile * TIL;
        for (int idx = tid; idx < 64 * TIL; idx += 256) {
            const int c  = idx >> 7;
            const int tl = idx & 127;
            const int t  = t0 + tl;
            float v = 0.f;
            if (c < CCH && t < TT) v = xb[c * TT + t];
            xs[c * 132 + tl] = v;
        }
        __syncthreads();

        if (tid < CCH) {
            const float4* rp = (const float4*)(xs + tid * 132);
#pragma unroll 8
            for (int tl = 0; tl < 32; tl++) {
                const float4 v = rp[tl];
                mysum += (v.x + v.y) + (v.z + v.w);
            }
        }

        if (act) {
            const float4* r0 = (const float4*)(xs + (4 * bi + 0) * 132);
            const float4* r1 = (const float4*)(xs + (4 * bi + 1) * 132);
            const float4* r2 = (const float4*)(xs + (4 * bi + 2) * 132);
            const float4* r3 = (const float4*)(xs + (4 * bi + 3) * 132);
            const float4* c0 = (const float4*)(xs + (4 * bj + 0) * 132);
            const float4* c1 = (const float4*)(xs + (4 * bj + 1) * 132);
            const float4* c2 = (const float4*)(xs + (4 * bj + 2) * 132);
            const float4* c3 = (const float4*)(xs + (4 * bj + 3) * 132);

#pragma unroll 2
            for (int tl = 0; tl < 32; tl++) {
                const float4 a0 = r0[tl], a1 = r1[tl], a2 = r2[tl], a3 = r3[tl];
                const float4 b0 = c0[tl], b1 = c1[tl], b2 = c2[tl], b3 = c3[tl];
#define DOT4(A, B) ((A.x * B.x + A.y * B.y) + (A.z * B.z + A.w * B.w))
                acc[0]  += DOT4(a0, b0); acc[1]  += DOT4(a0, b1);
                acc[2]  += DOT4(a0, b2); acc[3]  += DOT4(a0, b3);
                acc[4]  += DOT4(a1, b0); acc[5]  += DOT4(a1, b1);
                acc[6]  += DOT4(a1, b2); acc[7]  += DOT4(a1, b3);
                acc[8]  += DOT4(a2, b0); acc[9]  += DOT4(a2, b1);
                acc[10] += DOT4(a2, b2); acc[11] += DOT4(a2, b3);
                acc[12] += DOT4(a3, b0); acc[13] += DOT4(a3, b1);
                acc[14] += DOT4(a3, b2); acc[15] += DOT4(a3, b3);
#undef DOT4
            }
        }
        __syncthreads();
    }

    if (tid < 64) ssum[tid] = (tid < CCH) ? mysum : 0.f;
    __syncthreads();

    if (act) {
        float* outp = g_cx + b * 4096;
#pragma unroll
        for (int r = 0; r < 4; r++) {
#pragma unroll
            for (int u = 0; u < 4; u++) {
                const int i = 4 * bi + r;
                const int j = 4 * bj + u;
                const float v =
                    (acc[r * 4 + u] - ssum[i] * ssum[j] * (1.f / 2000.f)) * (1.f / 1999.f);
                outp[i * 64 + j] = v;
                outp[j * 64 + i] = v;
            }
        }
    }
}

// ---------------------------------------------------------------------------
// Kernel 2: A = W Cx W^T + eps I -> fused two-sided Jacobi eigh -> log-map ->
//           triu -> proj+relu -> head.  One CTA (256 thr) per batch.
// ---------------------------------------------------------------------------
__global__ __launch_bounds__(256, 2) void eig_kernel(
    const float* __restrict__ conv_w,
    const float* __restrict__ proj_w, const float* __restrict__ proj_b,
    const float* __restrict__ head_w, const float* __restrict__ head_b,
    float* __restrict__ out)
{
    __shared__ float Asm[64 * 65];                  // stride 65
    __shared__ __align__(16) float Vsm[64 * 64];    // stride 64 (float2 rows)
    __shared__ float Wbuf[62 * 62];                 // W in prologue; scratch after

    float* vec  = Wbuf;              // [1953]
    float* logl = Wbuf + 2048;       // [64]
    float* feat = Wbuf + 2112;       // [64]
    float* red  = Wbuf + 2176;       // [9]

    const int b    = blockIdx.x;
    const int tid  = threadIdx.x;
    const int wid  = tid >> 5;
    const int lane = tid & 31;
    const int ti   = tid >> 4;
    const int tj   = tid & 15;

    // ---- load Cx (into Asm) and W ----
    for (int idx = tid; idx < 4096; idx += 256)
        Asm[(idx >> 6) * 65 + (idx & 63)] = g_cx[b * 4096 + idx];
    for (int idx = tid; idx < 62 * 62; idx += 256) Wbuf[idx] = conv_w[idx];
    __syncthreads();

    // ---- M = W * Cx  -> Vsm ----
    {
        float acc[16];
#pragma unroll
        for (int r = 0; r < 16; r++) acc[r] = 0.f;
        for (int k = 0; k < 62; k++) {
            float wv[4], cv[4];
#pragma unroll
            for (int r = 0; r < 4; r++) {
                const int i = 4 * ti + r;
                wv[r] = (i < 62) ? Wbuf[i * 62 + k] : 0.f;
            }
#pragma unroll
            for (int u = 0; u < 4; u++) cv[u] = Asm[k * 65 + 4 * tj + u];
#pragma unroll
            for (int r = 0; r < 4; r++)
#pragma unroll
                for (int u = 0; u < 4; u++) acc[r * 4 + u] += wv[r] * cv[u];
        }
#pragma unroll
        for (int r = 0; r < 4; r++)
#pragma unroll
            for (int u = 0; u < 4; u++)
                Vsm[(4 * ti + r) * 64 + 4 * tj + u] = acc[r * 4 + u];
    }
    __syncthreads();

    // ---- A = M * W^T  -> Asm ----
    {
        float acc[16];
#pragma unroll
        for (int r = 0; r < 16; r++) acc[r] = 0.f;
        for (int k = 0; k < 62; k++) {
            float mv[4], wv[4];
#pragma unroll
            for (int r = 0; r < 4; r++) mv[r] = Vsm[(4 * ti + r) * 64 + k];
#pragma unroll
            for (int u = 0; u < 4; u++) {
                const int j = 4 * tj + u;
                wv[u] = (j < 62) ? Wbuf[j * 62 + k] : 0.f;
            }
#pragma unroll
            for (int r = 0; r < 4; r++)
#pragma unroll
                for (int u = 0; u < 4; u++) acc[r * 4 + u] += mv[r] * wv[u];
        }
#pragma unroll
        for (int r = 0; r < 4; r++)
#pragma unroll
            for (int u = 0; u < 4; u++)
                Asm[(4 * ti + r) * 65 + 4 * tj + u] = acc[r * 4 + u];
    }
    __syncthreads();

    // ---- symmetrize + SPD eps + pad diag ----
    {
        float v[16];
#pragma unroll
        for (int r = 0; r < 4; r++)
#pragma unroll
            for (int u = 0; u < 4; u++) {
                const int i = 4 * ti + r, j = 4 * tj + u;
                v[r * 4 + u] = 0.5f * (Asm[i * 65 + j] + Asm[j * 65 + i]);
            }
        __syncthreads();
#pragma unroll
        for (int r = 0; r < 4; r++)
#pragma unroll
            for (int u = 0; u < 4; u++) {
                const int i = 4 * ti + r, j = 4 * tj + u;
                float val = v[r * 4 + u];
                if (i == j) val = (i < 62) ? val + 1e-3f : 1.0f;
                Asm[i * 65 + j] = val;
            }
    }
    // V = I
    for (int idx = tid; idx < 4096; idx += 256)
        Vsm[idx] = ((idx >> 6) == (idx & 63)) ? 1.f : 0.f;
    __syncthreads();

    // ---- fused two-sided parallel Jacobi ----
    // Per round: 32 disjoint pairs partition indices 0..63. Blocks
    // {rows of pair kr} x {cols of pair kc} tile the matrix -> each thread
    // applies left rot (kr, broadcast-shfl'd) and right rot (kc = own lane)
    // to its 2x2 blocks in one pass. V rows updated with the same kr values.
    const float tol = 1e-5f;
    for (int sweep = 0; sweep < 9; sweep++) {
        for (int r = 0; r < 63; r++) {
            // rotation for pair k = lane (all warps compute all 32 redundantly)
            int p, q;
            if (lane == 0) { p = 63; q = r; }
            else {
                p = r + lane;      if (p >= 63) p -= 63;
                q = r + 63 - lane; if (q >= 63) q -= 63;
            }
            const float app = Asm[p * 65 + p];
            const float aqq = Asm[q * 65 + q];
            const float apq = Asm[p * 65 + q];
            float cO = 1.f, sO = 0.f;
            if (fabsf(apq) > 1e-12f) {
                const float tau = (aqq - app) / (2.f * apq);
                const float t2  = ((tau >= 0.f) ? 1.f : -1.f) /
                                  (fabsf(tau) + sqrtf(1.f + tau * tau));
                cO = rsqrtf(1.f + t2 * t2);
                sO = t2 * cO;
            }
            const int pqPack = p | (q << 8);
            const unsigned rotmask = __ballot_sync(0xffffffffu, sO != 0.f);

            if (rotmask != 0u) {
                __syncthreads();   // all rot-reads done before any writes
#pragma unroll
                for (int it = 0; it < 4; it++) {
                    const int   kk = 8 * it + wid;                 // warp-uniform
                    const float cr = __shfl_sync(0xffffffffu, cO, kk);
                    const float sr = __shfl_sync(0xffffffffu, sO, kk);
                    const int   pq = __shfl_sync(0xffffffffu, pqPack, kk);
                    const int   pr = pq & 255, qr = pq >> 8;
                    const int   rp = pr * 65, rq = qr * 65;

                    // A block: rows (pr,qr) x cols (p,q)
                    if (sr != 0.f || sO != 0.f) {
                        const float a00 = Asm[rp + p], a01 = Asm[rp + q];
                        const float a10 = Asm[rq + p], a11 = Asm[rq + q];
                        const float b00 = cr * a00 - sr * a10;
                        const float b01 = cr * a01 - sr * a11;
                        const float b10 = sr * a00 + cr * a10;
                        const float b11 = sr * a01 + cr * a11;
                        Asm[rp + p] = cO * b00 - sO * b01;
                        Asm[rp + q] = sO * b00 + cO * b01;
                        Asm[rq + p] = cO * b10 - sO * b11;
                        Asm[rq + q] = sO * b10 + cO * b11;
                    }
                    // V rows (pr,qr), column pair 2*lane
                    if (sr != 0.f) {
                        float2* vp = (float2*)(Vsm + pr * 64) + lane;
                        float2* vq = (float2*)(Vsm + qr * 64) + lane;
                        const float2 xp = *vp, xq = *vq;
                        float2 np, nq;
                        np.x = cr * xp.x - sr * xq.x;
                        np.y = cr * xp.y - sr * xq.y;
                        nq.x = sr * xp.x + cr * xq.x;
                        nq.y = sr * xp.y + cr * xq.y;
                        *vp = np; *vq = nq;
                    }
                }
                __syncthreads();   // writes visible before next round's rot-reads
            }
        }

        // convergence: max |offdiag|
        float m = 0.f;
        for (int idx = tid; idx < 4096; idx += 256) {
            const int i = idx >> 6, j = idx & 63;
            if (i != j) m = fmaxf(m, fabsf(Asm[i * 65 + j]));
        }
#pragma unroll
        for (int off = 16; off; off >>= 1)
            m = fmaxf(m, __shfl_down_sync(0xffffffffu, m, off));
        if (lane == 0) red[wid] = m;
        __syncthreads();
        if (tid == 0) {
            float mm = red[0];
#pragma unroll
            for (int w = 1; w < 8; w++) mm = fmaxf(mm, red[w]);
            red[8] = mm;
        }
        __syncthreads();
        if (red[8] < tol) break;
    }

    // ---- log eigenvalues ----
    if (tid < 64) {
        const float d = Asm[tid * 65 + tid];
        logl[tid] = logf(fmaxf(d, 1e-6f));
    }
    __syncthreads();
    // scale rows: Asm[k][i] = logl[k] * Q[k][i]
    for (int idx = tid; idx < 4096; idx += 256) {
        const int k = idx >> 6, i = idx & 63;
        Asm[k * 65 + i] = logl[k] * Vsm[idx];
    }
    __syncthreads();

    // ---- triu vectorize: vec(i,j) = sum_k logl[k] Q[k][i] Q[k][j] ----
    for (int idx = tid; idx < 1953; idx += 256) {
        int i = (int)((125.0f - sqrtf(15625.0f - 8.0f * (float)idx)) * 0.5f);
        if (i < 0) i = 0;
        if (i > 61) i = 61;
        while (i < 61 && (i + 1) * (125 - (i + 1)) / 2 <= idx) i++;
        while (i > 0 && i * (125 - i) / 2 > idx) i--;
        const int j = i + (idx - i * (125 - i) / 2);
        float acc = 0.f;
#pragma unroll 8
        for (int k = 0; k < 64; k++) acc += Asm[k * 65 + i] * Vsm[k * 64 + j];
        vec[idx] = acc;
    }
    __syncthreads();

    // ---- MLP: feat = relu(vec @ proj^T + b), 8 outputs per warp ----
    {
#pragma unroll
        for (int hh = 0; hh < 8; hh++) {
            const int h = (wid << 3) + hh;
            const float* pw = proj_w + h * 1953;
            float acc = 0.f;
            for (int i = lane; i < 1953; i += 32) acc += vec[i] * pw[i];
#pragma unroll
            for (int off = 16; off; off >>= 1)
                acc += __shfl_down_sync(0xffffffffu, acc, off);
            if (lane == 0) feat[h] = fmaxf(acc + proj_b[h], 0.f);
        }
    }
    __syncthreads();

    // ---- head: 3 logits ----
    if (tid < 3) {
        float acc = head_b[tid];
        const float* hw = head_w + tid * 64;
#pragma unroll
        for (int h = 0; h < 64; h++) acc += feat[h] * hw[h];
        out[b * 3 + tid] = acc;
    }
}

// ---------------------------------------------------------------------------
extern "C" void kernel_launch(void* const* d_in, const int* in_sizes, int n_in,
                              void* d_out, int out_size)
{
    const float* x      = (const float*)d_in[0];
    const float* conv_w = (const float*)d_in[1];
    // d_in[2] = conv_b: cancels exactly under mean-centering; unused.
    const float* proj_w = (const float*)d_in[3];
    const float* proj_b = (const float*)d_in[4];
    const float* head_w = (const float*)d_in[5];
    const float* head_b = (const float*)d_in[6];

    int B = in_sizes[0] / (CCH * TT);
    if (B > NB) B = NB;

    cov_kernel<<<B, 256>>>(x);
    eig_kernel<<<B, 256>>>(conv_w, proj_w, proj_b, head_w, head_b, (float*)d_out);
}